// round 7
// baseline (speedup 1.0000x reference)
#include <cuda_runtime.h>
#include <math.h>

#define NTOK 16384
#define CDIM 2048
#define NE   16
#define DE   128
#define HDIM 512

// ---------------- device scratch (static globals: no allocs allowed) -------
__device__ int g_count[NE];
__device__ int g_list[NE][NTOK];

__global__ void init_kernel() {
    if (threadIdx.x < NE) g_count[threadIdx.x] = 0;
}

// ---------------- gate: logits + zero-fill + compaction --------------------
// Block: 128 tokens x 16 experts, 128 threads, each thread 4 tok x 4 exp.
// fp32 per-64-chunk partials accumulated into fp64 masters (minimize
// threshold flips vs the fp32-BLAS reference).
#define GT  128
#define GKC 64

__global__ __launch_bounds__(128) void gate_kernel(
    const float* __restrict__ x, const float* __restrict__ gw,
    const float* __restrict__ gb, float* __restrict__ out)
{
    __shared__ float xs[GKC][GT + 4];
    __shared__ float ws[GKC][NE];
    __shared__ unsigned char act[GT][NE];

    const int tid  = threadIdx.x;
    const int t0   = blockIdx.x * GT;
    const int tok4 = (tid & 31) * 4;
    const int e4   = (tid >> 5) * 4;

    double acc[4][4];
#pragma unroll
    for (int i = 0; i < 4; i++)
#pragma unroll
        for (int j = 0; j < 4; j++) acc[i][j] = 0.0;

    for (int c0 = 0; c0 < CDIM; c0 += GKC) {
        // stage x chunk transposed [c][t]
        for (int i = tid; i < GT * GKC; i += 128) {
            int t = i >> 6, c = i & 63;
            xs[c][t] = x[(size_t)(t0 + t) * CDIM + c0 + c];
        }
        // stage gate_w chunk [c][e]
        for (int i = tid; i < NE * GKC; i += 128) {
            int e = i >> 6, c = i & 63;
            ws[c][e] = gw[e * CDIM + c0 + c];
        }
        __syncthreads();

        float f[4][4];
#pragma unroll
        for (int i = 0; i < 4; i++)
#pragma unroll
            for (int j = 0; j < 4; j++) f[i][j] = 0.0f;

#pragma unroll 16
        for (int c = 0; c < GKC; c++) {
            float4 xv = *(const float4*)&xs[c][tok4];
            float4 wv = *(const float4*)&ws[c][e4];
            float xr[4] = {xv.x, xv.y, xv.z, xv.w};
            float wr[4] = {wv.x, wv.y, wv.z, wv.w};
#pragma unroll
            for (int i = 0; i < 4; i++)
#pragma unroll
                for (int j = 0; j < 4; j++) f[i][j] += xr[i] * wr[j];
        }
#pragma unroll
        for (int i = 0; i < 4; i++)
#pragma unroll
            for (int j = 0; j < 4; j++) acc[i][j] += (double)f[i][j];
        __syncthreads();
    }

    // threshold (strict > 0, matching the reference)
#pragma unroll
    for (int i = 0; i < 4; i++)
#pragma unroll
        for (int j = 0; j < 4; j++) {
            float l = (float)acc[i][j] + gb[e4 + j];
            act[tok4 + i][e4 + j] = (l > 0.0f) ? 1 : 0;
        }
    __syncthreads();

    // zero the output blocks of inactive (t,e) pairs (out is poisoned)
    for (int i = tid; i < GT * NE * (DE / 4); i += 128) {
        int pair = i >> 5, q = i & 31;
        int t = pair >> 4, e = pair & 15;
        if (!act[t][e]) {
            float4 z = make_float4(0.f, 0.f, 0.f, 0.f);
            *(float4*)&out[(size_t)(t0 + t) * CDIM + e * DE + q * 4] = z;
        }
    }

    // compact active token ids per expert (one atomic per expert per block)
    if (tid < NE) {
        int e = tid, cnt = 0;
        for (int t = 0; t < GT; t++) cnt += act[t][e];
        int base = atomicAdd(&g_count[e], cnt);
        for (int t = 0; t < GT; t++)
            if (act[t][e]) g_list[e][base++] = t0 + t;
    }
}

// ---------------- expert MLP: compacted fc -> gelu -> proj -----------------
// Block = (expert, 128-token tile), 512 threads, ~170KB dynamic smem.
// GEMM1: 128tok x 64h x 128d per chunk (4x4 reg tile)
// GEMM2: 128tok x 128dout x 64h per chunk (4x8 reg tile, persistent accum)
#define MT   128
#define HC   64
#define XS_S (MT + 4)   // 132
#define FW_S (HC + 4)   // 68
#define HS_S (MT + 4)   // 132
#define PW_S (DE + 4)   // 132

#define SMEM_FLOATS (DE * XS_S + DE * FW_S + HC * HS_S + HC * PW_S)
#define SMEM_BYTES  (SMEM_FLOATS * 4 + MT * 4)

__global__ __launch_bounds__(512, 1) void expert_kernel(
    const float* __restrict__ x,
    const float* __restrict__ fcw, const float* __restrict__ fcb,
    const float* __restrict__ pjw, const float* __restrict__ pjb,
    float* __restrict__ out)
{
    const int e   = blockIdx.y;
    const int cnt = g_count[e];
    const int i0  = blockIdx.x * MT;
    if (i0 >= cnt) return;

    extern __shared__ float sm[];
    float* xs = sm;                      // [DE][XS_S]
    float* fw = xs + DE * XS_S;          // [DE][FW_S]
    float* hs = fw + DE * FW_S;          // [HC][HS_S]
    float* pw = hs + HC * HS_S;          // [HC][PW_S]
    int* toks = (int*)(pw + HC * PW_S);  // [MT]

    const int tid = threadIdx.x;
    if (tid < MT) {
        int idx = i0 + tid;
        toks[tid] = (idx < cnt) ? g_list[e][idx] : -1;
    }
    __syncthreads();

    // gather this expert's 128 strided channels: xc[t][d] = x[t][d*16+e]
    for (int i = tid; i < DE * MT; i += 512) {
        int d = i >> 7, j = i & 127;
        int t = toks[j];
        xs[d * XS_S + j] = (t >= 0) ? x[(size_t)t * CDIM + d * NE + e] : 0.0f;
    }

    const int tA = (tid & 31) * 4;   // token offset (both GEMMs)
    const int h4 = (tid >> 5) * 4;   // GEMM1 h offset
    const int d8 = (tid >> 5) * 8;   // GEMM2 dout offset

    float oacc[4][8];
#pragma unroll
    for (int i = 0; i < 4; i++)
#pragma unroll
        for (int j = 0; j < 8; j++) oacc[i][j] = 0.0f;

    for (int hc = 0; hc < HDIM; hc += HC) {
        // fc_w chunk transposed: fw[d][h] = fc_w[e][hc+h][d]
        for (int i = tid; i < HC * DE; i += 512) {
            int h = i >> 7, d = i & 127;
            fw[d * FW_S + h] = fcw[((size_t)e * HDIM + hc + h) * DE + d];
        }
        // proj_w chunk transposed: pw[h][dd] = proj_w[e][dd][hc+h]
        for (int i = tid; i < DE * HC; i += 512) {
            int dd = i >> 6, h = i & 63;
            pw[h * PW_S + dd] = pjw[((size_t)e * DE + dd) * HDIM + hc + h];
        }
        __syncthreads();

        // GEMM1: h[t][h] = sum_d xc[t][d] * fc_w[h][d]
        float hacc[4][4];
#pragma unroll
        for (int i = 0; i < 4; i++)
#pragma unroll
            for (int j = 0; j < 4; j++) hacc[i][j] = 0.0f;

#pragma unroll 16
        for (int d = 0; d < DE; d++) {
            float4 xv = *(const float4*)&xs[d * XS_S + tA];
            float4 wv = *(const float4*)&fw[d * FW_S + h4];
            float xr[4] = {xv.x, xv.y, xv.z, xv.w};
            float wr[4] = {wv.x, wv.y, wv.z, wv.w};
#pragma unroll
            for (int i = 0; i < 4; i++)
#pragma unroll
                for (int j = 0; j < 4; j++) hacc[i][j] += xr[i] * wr[j];
        }

        // bias + exact gelu, stage to smem transposed [h][t]
#pragma unroll
        for (int j = 0; j < 4; j++) {
            float b = fcb[e * HDIM + hc + h4 + j];
#pragma unroll
            for (int i = 0; i < 4; i++) {
                float v = hacc[i][j] + b;
                v = 0.5f * v * (1.0f + erff(v * 0.70710678118654752440f));
                hs[(h4 + j) * HS_S + tA + i] = v;
            }
        }
        __syncthreads();

        // GEMM2: out[t][dd] += sum_h act[t][h] * proj_w[dd][h]
#pragma unroll 8
        for (int h = 0; h < HC; h++) {
            float4 hv = *(const float4*)&hs[h * HS_S + tA];
            float4 p0 = *(const float4*)&pw[h * PW_S + d8];
            float4 p1 = *(const float4*)&pw[h * PW_S + d8 + 4];
            float hr[4] = {hv.x, hv.y, hv.z, hv.w};
            float pr[8] = {p0.x, p0.y, p0.z, p0.w, p1.x, p1.y, p1.z, p1.w};
#pragma unroll
            for (int i = 0; i < 4; i++)
#pragma unroll
                for (int j = 0; j < 8; j++) oacc[i][j] += hr[i] * pr[j];
        }
        __syncthreads();
    }

    // epilogue: + proj_b, store (active tokens => gate weight is exactly 1)
    float pb[8];
#pragma unroll
    for (int j = 0; j < 8; j++) pb[j] = pjb[e * DE + d8 + j];
#pragma unroll
    for (int i = 0; i < 4; i++) {
        int t = toks[tA + i];
        if (t < 0) continue;
        float* op = &out[(size_t)t * CDIM + e * DE + d8];
        float4 r0 = make_float4(oacc[i][0] + pb[0], oacc[i][1] + pb[1],
                                oacc[i][2] + pb[2], oacc[i][3] + pb[3]);
        float4 r1 = make_float4(oacc[i][4] + pb[4], oacc[i][5] + pb[5],
                                oacc[i][6] + pb[6], oacc[i][7] + pb[7]);
        *(float4*)op = r0;
        *(float4*)(op + 4) = r1;
    }
}

// ---------------- launch ----------------------------------------------------
extern "C" void kernel_launch(void* const* d_in, const int* in_sizes, int n_in,
                              void* d_out, int out_size)
{
    const float* x   = (const float*)d_in[0];
    const float* gw  = (const float*)d_in[1];
    const float* gb  = (const float*)d_in[2];
    const float* fcw = (const float*)d_in[3];
    const float* fcb = (const float*)d_in[4];
    const float* pjw = (const float*)d_in[5];
    const float* pjb = (const float*)d_in[6];
    float* out = (float*)d_out;

    init_kernel<<<1, 32>>>();
    gate_kernel<<<NTOK / GT, 128>>>(x, gw, gb, out);

    cudaFuncSetAttribute(expert_kernel,
                         cudaFuncAttributeMaxDynamicSharedMemorySize,
                         SMEM_BYTES);
    dim3 grid(NTOK / MT, NE);
    expert_kernel<<<grid, 512, SMEM_BYTES>>>(x, fcw, fcb, pjw, pjb, out);
}

// round 8
// speedup vs baseline: 1.0007x; 1.0007x over previous
#include <cuda_runtime.h>
#include <math.h>

#define NTOK 16384
#define CDIM 2048
#define NE   16
#define DE   128
#define HDIM 512

// ---------------- device scratch (static globals: no allocs allowed) -------
__device__ int g_count[NE];
__device__ int g_list[NE][NTOK];

__global__ void init_kernel() {
    if (threadIdx.x < NE) g_count[threadIdx.x] = 0;
}

// ---------------- gate: logits + zero-fill + compaction --------------------
// Block: 128 tokens x 16 experts, 128 threads, each thread 4 tok x 4 exp.
// fp32 per-64-chunk partials accumulated into fp64 masters (minimize
// threshold flips vs the fp32-BLAS reference).
#define GT  128
#define GKC 64

__global__ __launch_bounds__(128) void gate_kernel(
    const float* __restrict__ x, const float* __restrict__ gw,
    const float* __restrict__ gb, float* __restrict__ out)
{
    __shared__ float xs[GKC][GT + 4];
    __shared__ float ws[GKC][NE];
    __shared__ unsigned char act[GT][NE];

    const int tid  = threadIdx.x;
    const int t0   = blockIdx.x * GT;
    const int tok4 = (tid & 31) * 4;
    const int e4   = (tid >> 5) * 4;

    double acc[4][4];
#pragma unroll
    for (int i = 0; i < 4; i++)
#pragma unroll
        for (int j = 0; j < 4; j++) acc[i][j] = 0.0;

    for (int c0 = 0; c0 < CDIM; c0 += GKC) {
        // stage x chunk transposed [c][t]
        for (int i = tid; i < GT * GKC; i += 128) {
            int t = i >> 6, c = i & 63;
            xs[c][t] = x[(size_t)(t0 + t) * CDIM + c0 + c];
        }
        // stage gate_w chunk [c][e]
        for (int i = tid; i < NE * GKC; i += 128) {
            int e = i >> 6, c = i & 63;
            ws[c][e] = gw[e * CDIM + c0 + c];
        }
        __syncthreads();

        float f[4][4];
#pragma unroll
        for (int i = 0; i < 4; i++)
#pragma unroll
            for (int j = 0; j < 4; j++) f[i][j] = 0.0f;

#pragma unroll 16
        for (int c = 0; c < GKC; c++) {
            float4 xv = *(const float4*)&xs[c][tok4];
            float4 wv = *(const float4*)&ws[c][e4];
            float xr[4] = {xv.x, xv.y, xv.z, xv.w};
            float wr[4] = {wv.x, wv.y, wv.z, wv.w};
#pragma unroll
            for (int i = 0; i < 4; i++)
#pragma unroll
                for (int j = 0; j < 4; j++) f[i][j] += xr[i] * wr[j];
        }
#pragma unroll
        for (int i = 0; i < 4; i++)
#pragma unroll
            for (int j = 0; j < 4; j++) acc[i][j] += (double)f[i][j];
        __syncthreads();
    }

    // threshold (strict > 0, matching the reference)
#pragma unroll
    for (int i = 0; i < 4; i++)
#pragma unroll
        for (int j = 0; j < 4; j++) {
            float l = (float)acc[i][j] + gb[e4 + j];
            act[tok4 + i][e4 + j] = (l > 0.0f) ? 1 : 0;
        }
    __syncthreads();

    // zero the output blocks of inactive (t,e) pairs (out is poisoned)
    for (int i = tid; i < GT * NE * (DE / 4); i += 128) {
        int pair = i >> 5, q = i & 31;
        int t = pair >> 4, e = pair & 15;
        if (!act[t][e]) {
            float4 z = make_float4(0.f, 0.f, 0.f, 0.f);
            *(float4*)&out[(size_t)(t0 + t) * CDIM + e * DE + q * 4] = z;
        }
    }

    // compact active token ids per expert (one atomic per expert per block)
    if (tid < NE) {
        int e = tid, cnt = 0;
        for (int t = 0; t < GT; t++) cnt += act[t][e];
        int base = atomicAdd(&g_count[e], cnt);
        for (int t = 0; t < GT; t++)
            if (act[t][e]) g_list[e][base++] = t0 + t;
    }
}

// ---------------- expert MLP: compacted fc -> gelu -> proj -----------------
// Block = (expert, 128-token tile), 512 threads, ~170KB dynamic smem.
// GEMM1: 128tok x 64h x 128d per chunk (4x4 reg tile)
// GEMM2: 128tok x 128dout x 64h per chunk (4x8 reg tile, persistent accum)
#define MT   128
#define HC   64
#define XS_S (MT + 4)   // 132
#define FW_S (HC + 4)   // 68
#define HS_S (MT + 4)   // 132
#define PW_S (DE + 4)   // 132

#define SMEM_FLOATS (DE * XS_S + DE * FW_S + HC * HS_S + HC * PW_S)
#define SMEM_BYTES  (SMEM_FLOATS * 4 + MT * 4)

__global__ __launch_bounds__(512, 1) void expert_kernel(
    const float* __restrict__ x,
    const float* __restrict__ fcw, const float* __restrict__ fcb,
    const float* __restrict__ pjw, const float* __restrict__ pjb,
    float* __restrict__ out)
{
    const int e   = blockIdx.y;
    const int cnt = g_count[e];
    const int i0  = blockIdx.x * MT;
    if (i0 >= cnt) return;

    extern __shared__ float sm[];
    float* xs = sm;                      // [DE][XS_S]
    float* fw = xs + DE * XS_S;          // [DE][FW_S]
    float* hs = fw + DE * FW_S;          // [HC][HS_S]
    float* pw = hs + HC * HS_S;          // [HC][PW_S]
    int* toks = (int*)(pw + HC * PW_S);  // [MT]

    const int tid = threadIdx.x;
    if (tid < MT) {
        int idx = i0 + tid;
        toks[tid] = (idx < cnt) ? g_list[e][idx] : -1;
    }
    __syncthreads();

    // gather this expert's 128 strided channels: xc[t][d] = x[t][d*16+e]
    for (int i = tid; i < DE * MT; i += 512) {
        int d = i >> 7, j = i & 127;
        int t = toks[j];
        xs[d * XS_S + j] = (t >= 0) ? x[(size_t)t * CDIM + d * NE + e] : 0.0f;
    }

    const int tA = (tid & 31) * 4;   // token offset (both GEMMs)
    const int h4 = (tid >> 5) * 4;   // GEMM1 h offset
    const int d8 = (tid >> 5) * 8;   // GEMM2 dout offset

    float oacc[4][8];
#pragma unroll
    for (int i = 0; i < 4; i++)
#pragma unroll
        for (int j = 0; j < 8; j++) oacc[i][j] = 0.0f;

    for (int hc = 0; hc < HDIM; hc += HC) {
        // fc_w chunk transposed: fw[d][h] = fc_w[e][hc+h][d]
        for (int i = tid; i < HC * DE; i += 512) {
            int h = i >> 7, d = i & 127;
            fw[d * FW_S + h] = fcw[((size_t)e * HDIM + hc + h) * DE + d];
        }
        // proj_w chunk transposed: pw[h][dd] = proj_w[e][dd][hc+h]
        for (int i = tid; i < DE * HC; i += 512) {
            int dd = i >> 6, h = i & 63;
            pw[h * PW_S + dd] = pjw[((size_t)e * DE + dd) * HDIM + hc + h];
        }
        __syncthreads();

        // GEMM1: h[t][h] = sum_d xc[t][d] * fc_w[h][d]
        float hacc[4][4];
#pragma unroll
        for (int i = 0; i < 4; i++)
#pragma unroll
            for (int j = 0; j < 4; j++) hacc[i][j] = 0.0f;

#pragma unroll 16
        for (int d = 0; d < DE; d++) {
            float4 xv = *(const float4*)&xs[d * XS_S + tA];
            float4 wv = *(const float4*)&fw[d * FW_S + h4];
            float xr[4] = {xv.x, xv.y, xv.z, xv.w};
            float wr[4] = {wv.x, wv.y, wv.z, wv.w};
#pragma unroll
            for (int i = 0; i < 4; i++)
#pragma unroll
                for (int j = 0; j < 4; j++) hacc[i][j] += xr[i] * wr[j];
        }

        // bias + exact gelu, stage to smem transposed [h][t]
#pragma unroll
        for (int j = 0; j < 4; j++) {
            float b = fcb[e * HDIM + hc + h4 + j];
#pragma unroll
            for (int i = 0; i < 4; i++) {
                float v = hacc[i][j] + b;
                v = 0.5f * v * (1.0f + erff(v * 0.70710678118654752440f));
                hs[(h4 + j) * HS_S + tA + i] = v;
            }
        }
        __syncthreads();

        // GEMM2: out[t][dd] += sum_h act[t][h] * proj_w[dd][h]
#pragma unroll 8
        for (int h = 0; h < HC; h++) {
            float4 hv = *(const float4*)&hs[h * HS_S + tA];
            float4 p0 = *(const float4*)&pw[h * PW_S + d8];
            float4 p1 = *(const float4*)&pw[h * PW_S + d8 + 4];
            float hr[4] = {hv.x, hv.y, hv.z, hv.w};
            float pr[8] = {p0.x, p0.y, p0.z, p0.w, p1.x, p1.y, p1.z, p1.w};
#pragma unroll
            for (int i = 0; i < 4; i++)
#pragma unroll
                for (int j = 0; j < 8; j++) oacc[i][j] += hr[i] * pr[j];
        }
        __syncthreads();
    }

    // epilogue: + proj_b, store (active tokens => gate weight is exactly 1)
    float pb[8];
#pragma unroll
    for (int j = 0; j < 8; j++) pb[j] = pjb[e * DE + d8 + j];
#pragma unroll
    for (int i = 0; i < 4; i++) {
        int t = toks[tA + i];
        if (t < 0) continue;
        float* op = &out[(size_t)t * CDIM + e * DE + d8];
        float4 r0 = make_float4(oacc[i][0] + pb[0], oacc[i][1] + pb[1],
                                oacc[i][2] + pb[2], oacc[i][3] + pb[3]);
        float4 r1 = make_float4(oacc[i][4] + pb[4], oacc[i][5] + pb[5],
                                oacc[i][6] + pb[6], oacc[i][7] + pb[7]);
        *(float4*)op = r0;
        *(float4*)(op + 4) = r1;
    }
}

// ---------------- launch ----------------------------------------------------
extern "C" void kernel_launch(void* const* d_in, const int* in_sizes, int n_in,
                              void* d_out, int out_size)
{
    const float* x   = (const float*)d_in[0];
    const float* gw  = (const float*)d_in[1];
    const float* gb  = (const float*)d_in[2];
    const float* fcw = (const float*)d_in[3];
    const float* fcb = (const float*)d_in[4];
    const float* pjw = (const float*)d_in[5];
    const float* pjb = (const float*)d_in[6];
    float* out = (float*)d_out;

    init_kernel<<<1, 32>>>();
    gate_kernel<<<NTOK / GT, 128>>>(x, gw, gb, out);

    cudaFuncSetAttribute(expert_kernel,
                         cudaFuncAttributeMaxDynamicSharedMemorySize,
                         SMEM_BYTES);
    dim3 grid(NTOK / MT, NE);
    expert_kernel<<<grid, 512, SMEM_BYTES>>>(x, fcw, fcb, pjw, pjb, out);
}

// round 9
// speedup vs baseline: 1.0279x; 1.0272x over previous
#include <cuda_runtime.h>
#include <math.h>

#define NTOK 16384
#define CDIM 2048
#define NE   16
#define DE   128
#define HDIM 512

// ---------------- packed f32x2 helpers (Blackwell FFMA2 path) ---------------
__device__ __forceinline__ unsigned long long pk2(float a, float b) {
    unsigned long long r;
    asm("mov.b64 %0, {%1, %2};" : "=l"(r) : "f"(a), "f"(b));
    return r;
}
__device__ __forceinline__ void upk2(unsigned long long v, float& a, float& b) {
    asm("mov.b64 {%0, %1}, %2;" : "=f"(a), "=f"(b) : "l"(v));
}
#define FMA2(acc, a, b) \
    asm("fma.rn.f32x2 %0, %1, %2, %0;" : "+l"(acc) : "l"(a), "l"(b))

// ---------------- device scratch (static globals: no allocs allowed) -------
__device__ int g_count[NE];
__device__ int g_list[NE][NTOK];

__global__ void init_kernel() {
    if (threadIdx.x < NE) g_count[threadIdx.x] = 0;
}

// ---------------- gate: logits + zero-fill + compaction --------------------
// Block: 128 tokens x 16 experts, 128 threads, each thread 4 tok x 4 exp.
// Packed f32x2 per-64-chunk partials accumulated into fp64 masters
// (minimize threshold flips vs the fp32-BLAS reference).
#define GT  128
#define GKC 64

__global__ __launch_bounds__(128) void gate_kernel(
    const float* __restrict__ x, const float* __restrict__ gw,
    const float* __restrict__ gb, float* __restrict__ out)
{
    __shared__ float xs[GKC][GT + 4];
    __shared__ float ws[GKC][NE];
    __shared__ unsigned char act[GT][NE];

    const int tid  = threadIdx.x;
    const int t0   = blockIdx.x * GT;
    const int tok4 = (tid & 31) * 4;
    const int e4   = (tid >> 5) * 4;

    double acc[4][4];
#pragma unroll
    for (int i = 0; i < 4; i++)
#pragma unroll
        for (int j = 0; j < 4; j++) acc[i][j] = 0.0;

    for (int c0 = 0; c0 < CDIM; c0 += GKC) {
        for (int i = tid; i < GT * GKC; i += 128) {
            int t = i >> 6, c = i & 63;
            xs[c][t] = x[(size_t)(t0 + t) * CDIM + c0 + c];
        }
        for (int i = tid; i < NE * GKC; i += 128) {
            int e = i >> 6, c = i & 63;
            ws[c][e] = gw[e * CDIM + c0 + c];
        }
        __syncthreads();

        unsigned long long f2[4][2];
#pragma unroll
        for (int i = 0; i < 4; i++) { f2[i][0] = 0ull; f2[i][1] = 0ull; }

#pragma unroll 8
        for (int c = 0; c < GKC; c++) {
            float4 xv = *(const float4*)&xs[c][tok4];
            ulonglong2 wv = *(const ulonglong2*)&ws[c][e4];
            unsigned long long b0 = pk2(xv.x, xv.x);
            unsigned long long b1 = pk2(xv.y, xv.y);
            unsigned long long b2 = pk2(xv.z, xv.z);
            unsigned long long b3 = pk2(xv.w, xv.w);
            FMA2(f2[0][0], b0, wv.x); FMA2(f2[0][1], b0, wv.y);
            FMA2(f2[1][0], b1, wv.x); FMA2(f2[1][1], b1, wv.y);
            FMA2(f2[2][0], b2, wv.x); FMA2(f2[2][1], b2, wv.y);
            FMA2(f2[3][0], b3, wv.x); FMA2(f2[3][1], b3, wv.y);
        }
#pragma unroll
        for (int i = 0; i < 4; i++)
#pragma unroll
            for (int jp = 0; jp < 2; jp++) {
                float lo, hi; upk2(f2[i][jp], lo, hi);
                acc[i][2 * jp]     += (double)lo;
                acc[i][2 * jp + 1] += (double)hi;
            }
        __syncthreads();
    }

    // threshold (strict > 0, matching the reference)
#pragma unroll
    for (int i = 0; i < 4; i++)
#pragma unroll
        for (int j = 0; j < 4; j++) {
            float l = (float)acc[i][j] + gb[e4 + j];
            act[tok4 + i][e4 + j] = (l > 0.0f) ? 1 : 0;
        }
    __syncthreads();

    // zero the output blocks of inactive (t,e) pairs (out is poisoned)
    for (int i = tid; i < GT * NE * (DE / 4); i += 128) {
        int pair = i >> 5, q = i & 31;
        int t = pair >> 4, e = pair & 15;
        if (!act[t][e]) {
            float4 z = make_float4(0.f, 0.f, 0.f, 0.f);
            *(float4*)&out[(size_t)(t0 + t) * CDIM + e * DE + q * 4] = z;
        }
    }

    // compact active token ids per expert (one atomic per expert per block)
    if (tid < NE) {
        int e = tid, cnt = 0;
        for (int t = 0; t < GT; t++) cnt += act[t][e];
        int base = atomicAdd(&g_count[e], cnt);
        for (int t = 0; t < GT; t++)
            if (act[t][e]) g_list[e][base++] = t0 + t;
    }
}

// ---------------- expert MLP: compacted fc -> gelu -> proj -----------------
// Block = (expert, 128-token tile), 512 threads, ~170KB dynamic smem.
// Inner loops use packed fma.rn.f32x2 (FFMA2): 2x fp32 FMA throughput.
#define MT   128
#define HC   64
#define XS_S (MT + 4)   // 132
#define FW_S (HC + 4)   // 68
#define HS_S (MT + 4)   // 132
#define PW_S (DE + 4)   // 132

#define SMEM_FLOATS (DE * XS_S + DE * FW_S + HC * HS_S + HC * PW_S)
#define SMEM_BYTES  (SMEM_FLOATS * 4 + MT * 4)

__global__ __launch_bounds__(512, 1) void expert_kernel(
    const float* __restrict__ x,
    const float* __restrict__ fcw, const float* __restrict__ fcb,
    const float* __restrict__ pjw, const float* __restrict__ pjb,
    float* __restrict__ out)
{
    const int e   = blockIdx.y;
    const int cnt = g_count[e];
    const int i0  = blockIdx.x * MT;
    if (i0 >= cnt) return;

    extern __shared__ float sm[];
    float* xs = sm;                      // [DE][XS_S]
    float* fw = xs + DE * XS_S;          // [DE][FW_S]
    float* hs = fw + DE * FW_S;          // [HC][HS_S]
    float* pw = hs + HC * HS_S;          // [HC][PW_S]
    int* toks = (int*)(pw + HC * PW_S);  // [MT]

    const int tid = threadIdx.x;
    if (tid < MT) {
        int idx = i0 + tid;
        toks[tid] = (idx < cnt) ? g_list[e][idx] : -1;
    }
    __syncthreads();

    // gather this expert's 128 strided channels: xc[t][d] = x[t][d*16+e]
    for (int i = tid; i < DE * MT; i += 512) {
        int d = i >> 7, j = i & 127;
        int t = toks[j];
        xs[d * XS_S + j] = (t >= 0) ? x[(size_t)t * CDIM + d * NE + e] : 0.0f;
    }

    const int tA = (tid & 31) * 4;   // token offset (both GEMMs)
    const int h4 = (tid >> 5) * 4;   // GEMM1 h offset
    const int d8 = (tid >> 5) * 8;   // GEMM2 dout offset

    unsigned long long oacc2[4][4];  // [token][dd-pair], dd = d8 + 2*jp + {0,1}
#pragma unroll
    for (int i = 0; i < 4; i++)
#pragma unroll
        for (int j = 0; j < 4; j++) oacc2[i][j] = 0ull;

    for (int hc = 0; hc < HDIM; hc += HC) {
        // fc_w chunk transposed: fw[d][h] = fc_w[e][hc+h][d]
        for (int i = tid; i < HC * DE; i += 512) {
            int h = i >> 7, d = i & 127;
            fw[d * FW_S + h] = fcw[((size_t)e * HDIM + hc + h) * DE + d];
        }
        // proj_w chunk transposed: pw[h][dd] = proj_w[e][dd][hc+h]
        for (int i = tid; i < DE * HC; i += 512) {
            int dd = i >> 6, h = i & 63;
            pw[h * PW_S + dd] = pjw[((size_t)e * DE + dd) * HDIM + hc + h];
        }
        __syncthreads();

        // GEMM1: h[t][h] = sum_d xc[t][d] * fc_w[h][d]   (packed over h-pairs)
        unsigned long long hacc2[4][2];
#pragma unroll
        for (int i = 0; i < 4; i++) { hacc2[i][0] = 0ull; hacc2[i][1] = 0ull; }

#pragma unroll 8
        for (int d = 0; d < DE; d++) {
            float4 xv = *(const float4*)&xs[d * XS_S + tA];
            ulonglong2 wv = *(const ulonglong2*)&fw[d * FW_S + h4];
            unsigned long long b0 = pk2(xv.x, xv.x);
            unsigned long long b1 = pk2(xv.y, xv.y);
            unsigned long long b2 = pk2(xv.z, xv.z);
            unsigned long long b3 = pk2(xv.w, xv.w);
            FMA2(hacc2[0][0], b0, wv.x); FMA2(hacc2[0][1], b0, wv.y);
            FMA2(hacc2[1][0], b1, wv.x); FMA2(hacc2[1][1], b1, wv.y);
            FMA2(hacc2[2][0], b2, wv.x); FMA2(hacc2[2][1], b2, wv.y);
            FMA2(hacc2[3][0], b3, wv.x); FMA2(hacc2[3][1], b3, wv.y);
        }

        // bias + exact gelu, stage to smem transposed [h][t]
#pragma unroll
        for (int jp = 0; jp < 2; jp++) {
            float b0 = fcb[e * HDIM + hc + h4 + 2 * jp];
            float b1 = fcb[e * HDIM + hc + h4 + 2 * jp + 1];
#pragma unroll
            for (int i = 0; i < 4; i++) {
                float v0, v1; upk2(hacc2[i][jp], v0, v1);
                v0 += b0;
                v0 = 0.5f * v0 * (1.0f + erff(v0 * 0.70710678118654752440f));
                hs[(h4 + 2 * jp) * HS_S + tA + i] = v0;
                v1 += b1;
                v1 = 0.5f * v1 * (1.0f + erff(v1 * 0.70710678118654752440f));
                hs[(h4 + 2 * jp + 1) * HS_S + tA + i] = v1;
            }
        }
        __syncthreads();

        // GEMM2: out[t][dd] += sum_h act[t][h] * proj_w[dd][h] (packed dd-pairs)
#pragma unroll 8
        for (int h = 0; h < HC; h++) {
            float4 hv = *(const float4*)&hs[h * HS_S + tA];
            ulonglong2 p0 = *(const ulonglong2*)&pw[h * PW_S + d8];
            ulonglong2 p1 = *(const ulonglong2*)&pw[h * PW_S + d8 + 4];
            unsigned long long b0 = pk2(hv.x, hv.x);
            unsigned long long b1 = pk2(hv.y, hv.y);
            unsigned long long b2 = pk2(hv.z, hv.z);
            unsigned long long b3 = pk2(hv.w, hv.w);
            FMA2(oacc2[0][0], b0, p0.x); FMA2(oacc2[0][1], b0, p0.y);
            FMA2(oacc2[0][2], b0, p1.x); FMA2(oacc2[0][3], b0, p1.y);
            FMA2(oacc2[1][0], b1, p0.x); FMA2(oacc2[1][1], b1, p0.y);
            FMA2(oacc2[1][2], b1, p1.x); FMA2(oacc2[1][3], b1, p1.y);
            FMA2(oacc2[2][0], b2, p0.x); FMA2(oacc2[2][1], b2, p0.y);
            FMA2(oacc2[2][2], b2, p1.x); FMA2(oacc2[2][3], b2, p1.y);
            FMA2(oacc2[3][0], b3, p0.x); FMA2(oacc2[3][1], b3, p0.y);
            FMA2(oacc2[3][2], b3, p1.x); FMA2(oacc2[3][3], b3, p1.y);
        }
        __syncthreads();
    }

    // epilogue: + proj_b, store (active tokens => gate weight is exactly 1)
    float pb[8];
#pragma unroll
    for (int j = 0; j < 8; j++) pb[j] = pjb[e * DE + d8 + j];
#pragma unroll
    for (int i = 0; i < 4; i++) {
        int t = toks[tA + i];
        if (t < 0) continue;
        float o[8];
#pragma unroll
        for (int jp = 0; jp < 4; jp++)
            upk2(oacc2[i][jp], o[2 * jp], o[2 * jp + 1]);
        float* op = &out[(size_t)t * CDIM + e * DE + d8];
        float4 r0 = make_float4(o[0] + pb[0], o[1] + pb[1],
                                o[2] + pb[2], o[3] + pb[3]);
        float4 r1 = make_float4(o[4] + pb[4], o[5] + pb[5],
                                o[6] + pb[6], o[7] + pb[7]);
        *(float4*)op = r0;
        *(float4*)(op + 4) = r1;
    }
}

// ---------------- launch ----------------------------------------------------
extern "C" void kernel_launch(void* const* d_in, const int* in_sizes, int n_in,
                              void* d_out, int out_size)
{
    const float* x   = (const float*)d_in[0];
    const float* gw  = (const float*)d_in[1];
    const float* gb  = (const float*)d_in[2];
    const float* fcw = (const float*)d_in[3];
    const float* fcb = (const float*)d_in[4];
    const float* pjw = (const float*)d_in[5];
    const float* pjb = (const float*)d_in[6];
    float* out = (float*)d_out;

    init_kernel<<<1, 32>>>();
    gate_kernel<<<NTOK / GT, 128>>>(x, gw, gb, out);

    cudaFuncSetAttribute(expert_kernel,
                         cudaFuncAttributeMaxDynamicSharedMemorySize,
                         SMEM_BYTES);
    dim3 grid(NTOK / MT, NE);
    expert_kernel<<<grid, 512, SMEM_BYTES>>>(x, fcw, fcb, pjw, pjb, out);
}

// round 11
// speedup vs baseline: 1.2885x; 1.2535x over previous
#include <cuda_runtime.h>
#include <cuda_bf16.h>
#include <math.h>
#include <stdint.h>

#define NTOK 16384
#define CDIM 2048
#define NE   16
#define DE   128
#define HDIM 512

// ---------------- device scratch ----------------
__device__ int g_count[NE];
__device__ int g_list[NE][NTOK];

__global__ void init_kernel() {
    if (threadIdx.x < NE) g_count[threadIdx.x] = 0;
}

// ======================= gate (exact path, unchanged) =======================
#define GT  128
#define GKC 64
__device__ __forceinline__ unsigned long long pk2(float a, float b) {
    unsigned long long r;
    asm("mov.b64 %0, {%1, %2};" : "=l"(r) : "f"(a), "f"(b));
    return r;
}
__device__ __forceinline__ void upk2(unsigned long long v, float& a, float& b) {
    asm("mov.b64 {%0, %1}, %2;" : "=f"(a), "=f"(b) : "l"(v));
}
#define FMA2(acc, a, b) \
    asm("fma.rn.f32x2 %0, %1, %2, %0;" : "+l"(acc) : "l"(a), "l"(b))

__global__ __launch_bounds__(128) void gate_kernel(
    const float* __restrict__ x, const float* __restrict__ gw,
    const float* __restrict__ gb, float* __restrict__ out)
{
    __shared__ float xs[GKC][GT + 4];
    __shared__ float ws[GKC][NE];
    __shared__ unsigned char act[GT][NE];

    const int tid  = threadIdx.x;
    const int t0   = blockIdx.x * GT;
    const int tok4 = (tid & 31) * 4;
    const int e4   = (tid >> 5) * 4;

    double acc[4][4];
#pragma unroll
    for (int i = 0; i < 4; i++)
#pragma unroll
        for (int j = 0; j < 4; j++) acc[i][j] = 0.0;

    for (int c0 = 0; c0 < CDIM; c0 += GKC) {
        for (int i = tid; i < GT * GKC; i += 128) {
            int t = i >> 6, c = i & 63;
            xs[c][t] = x[(size_t)(t0 + t) * CDIM + c0 + c];
        }
        for (int i = tid; i < NE * GKC; i += 128) {
            int e = i >> 6, c = i & 63;
            ws[c][e] = gw[e * CDIM + c0 + c];
        }
        __syncthreads();

        unsigned long long f2[4][2];
#pragma unroll
        for (int i = 0; i < 4; i++) { f2[i][0] = 0ull; f2[i][1] = 0ull; }

#pragma unroll 8
        for (int c = 0; c < GKC; c++) {
            float4 xv = *(const float4*)&xs[c][tok4];
            ulonglong2 wv = *(const ulonglong2*)&ws[c][e4];
            unsigned long long b0 = pk2(xv.x, xv.x);
            unsigned long long b1 = pk2(xv.y, xv.y);
            unsigned long long b2 = pk2(xv.z, xv.z);
            unsigned long long b3 = pk2(xv.w, xv.w);
            FMA2(f2[0][0], b0, wv.x); FMA2(f2[0][1], b0, wv.y);
            FMA2(f2[1][0], b1, wv.x); FMA2(f2[1][1], b1, wv.y);
            FMA2(f2[2][0], b2, wv.x); FMA2(f2[2][1], b2, wv.y);
            FMA2(f2[3][0], b3, wv.x); FMA2(f2[3][1], b3, wv.y);
        }
#pragma unroll
        for (int i = 0; i < 4; i++)
#pragma unroll
            for (int jp = 0; jp < 2; jp++) {
                float lo, hi; upk2(f2[i][jp], lo, hi);
                acc[i][2 * jp]     += (double)lo;
                acc[i][2 * jp + 1] += (double)hi;
            }
        __syncthreads();
    }

#pragma unroll
    for (int i = 0; i < 4; i++)
#pragma unroll
        for (int j = 0; j < 4; j++) {
            float l = (float)acc[i][j] + gb[e4 + j];
            act[tok4 + i][e4 + j] = (l > 0.0f) ? 1 : 0;
        }
    __syncthreads();

    for (int i = tid; i < GT * NE * (DE / 4); i += 128) {
        int pair = i >> 5, q = i & 31;
        int t = pair >> 4, e = pair & 15;
        if (!act[t][e]) {
            float4 z = make_float4(0.f, 0.f, 0.f, 0.f);
            *(float4*)&out[(size_t)(t0 + t) * CDIM + e * DE + q * 4] = z;
        }
    }
    if (tid < NE) {
        int e = tid, cnt = 0;
        for (int t = 0; t < GT; t++) cnt += act[t][e];
        int base = atomicAdd(&g_count[e], cnt);
        for (int t = 0; t < GT; t++)
            if (act[t][e]) g_list[e][base++] = t0 + t;
    }
}

// ======================= expert MLP on mma.sync bf16 ========================
// Block = (expert, 128-token tile), 256 threads / 8 warps, occ 1.
// Warp tile = 32 tok x 64 cols. h chunked by 128 (4 iters). D2 persists in
// registers across chunks. 3-way bf16 split: Ah*Bh + Ah*Bl + Al*Bh.
#define MT 128
#define SB 136                   // smem row stride in bf16 (272 B: bank-shift 4)
#define ROWB 272                 // row stride bytes
#define TILE_B (128 * ROWB)      // 34816 B per 128x128 bf16 tile

#define OFF_A1H 0
#define OFF_A1L (OFF_A1H + TILE_B)
#define OFF_A2H (OFF_A1L + TILE_B)
#define OFF_A2L (OFF_A2H + TILE_B)
#define OFF_BH  (OFF_A2L + TILE_B)
#define OFF_BL  (OFF_BH  + TILE_B)
#define OFF_TOK (OFF_BL  + TILE_B)
#define SMEM_TOTAL (OFF_TOK + 512 + 128)

__device__ __forceinline__ void mma16816(float* d, const uint32_t* a,
                                         const uint32_t* b) {
    asm volatile(
        "mma.sync.aligned.m16n8k16.row.col.f32.bf16.bf16.f32 "
        "{%0,%1,%2,%3}, {%4,%5,%6,%7}, {%8,%9}, {%0,%1,%2,%3};"
        : "+f"(d[0]), "+f"(d[1]), "+f"(d[2]), "+f"(d[3])
        : "r"(a[0]), "r"(a[1]), "r"(a[2]), "r"(a[3]), "r"(b[0]), "r"(b[1]));
}

__device__ __forceinline__ unsigned long long pack4bf(float a, float b,
                                                      float c, float d) {
    __nv_bfloat162 lo = __floats2bfloat162_rn(a, b);
    __nv_bfloat162 hi = __floats2bfloat162_rn(c, d);
    unsigned int ulo = *(unsigned int*)&lo, uhi = *(unsigned int*)&hi;
    return (unsigned long long)ulo | ((unsigned long long)uhi << 32);
}
__device__ __forceinline__ uint32_t pack2bf(float a, float b) {
    __nv_bfloat162 p = __floats2bfloat162_rn(a, b);
    return *(uint32_t*)&p;
}

// one (A,B) MMA pass over a 128-K chunk, accumulating d[16][4]
// A rows: row0..row0+31 (tokens), B rows: ncol0..ncol0+63 (output cols)
__device__ __forceinline__ void mma_pass(const char* __restrict__ A,
                                         const char* __restrict__ B,
                                         float (*d)[4], int row0, int ncol0,
                                         int g, int c) {
#pragma unroll
    for (int kt = 0; kt < 8; kt++) {
        uint32_t a[2][4];
        const char* ar = A + (row0 + g) * ROWB + kt * 32 + c * 4;
#pragma unroll
        for (int mt = 0; mt < 2; mt++) {
            const char* am = ar + mt * (16 * ROWB);
            a[mt][0] = *(const uint32_t*)(am);
            a[mt][1] = *(const uint32_t*)(am + 8 * ROWB);
            a[mt][2] = *(const uint32_t*)(am + 16);
            a[mt][3] = *(const uint32_t*)(am + 8 * ROWB + 16);
        }
#pragma unroll
        for (int nt = 0; nt < 8; nt++) {
            const char* br = B + (ncol0 + nt * 8 + g) * ROWB + kt * 32 + c * 4;
            uint32_t b[2];
            b[0] = *(const uint32_t*)(br);
            b[1] = *(const uint32_t*)(br + 16);
            mma16816(d[nt], a[0], b);
            mma16816(d[8 + nt], a[1], b);
        }
    }
}

__global__ __launch_bounds__(256) void expert_kernel(
    const float* __restrict__ x,
    const float* __restrict__ fcw, const float* __restrict__ fcb,
    const float* __restrict__ pjw, const float* __restrict__ pjb,
    float* __restrict__ out)
{
    const int e   = blockIdx.y;
    const int cnt = g_count[e];
    const int i0  = blockIdx.x * MT;
    if (i0 >= cnt) return;

    extern __shared__ char sm[];
    int* toks = (int*)(sm + OFF_TOK);

    const int tid  = threadIdx.x;
    const int wid  = tid >> 5;
    const int lane = tid & 31;
    const int g    = lane >> 2;
    const int c    = lane & 3;
    const int mg   = wid & 3;    // token group: rows 32*mg..+31
    const int ng   = wid >> 2;   // col group:   cols 64*ng..+63
    const int row0 = 32 * mg;
    const int col0 = 64 * ng;

    if (tid < MT) {
        int idx = i0 + tid;
        toks[tid] = (idx < cnt) ? g_list[e][idx] : -1;
    }
    __syncthreads();

    // ---- A1: gather x strided channels, hi/lo split -> [tok][d] bf16
    for (int i = tid; i < MT * DE; i += 256) {
        int j = i & 127, d = i >> 7;
        int t = toks[j];
        float f = (t >= 0) ? x[(size_t)t * CDIM + d * NE + e] : 0.0f;
        __nv_bfloat16 hb = __float2bfloat16_rn(f);
        float lf = f - __bfloat162float(hb);
        uint32_t o = (uint32_t)(j * ROWB + d * 2);
        *(__nv_bfloat16*)(sm + OFF_A1H + o) = hb;
        *(__nv_bfloat16*)(sm + OFF_A1L + o) = __float2bfloat16_rn(lf);
    }

    float d2[16][4];
#pragma unroll
    for (int i = 0; i < 16; i++)
#pragma unroll
        for (int q = 0; q < 4; q++) d2[i][q] = 0.0f;

    for (int hc = 0; hc < 4; hc++) {
        // ---- B := fc_w chunk [h 128][d 128], hi/lo split
        for (int gi = tid; gi < 128 * 32; gi += 256) {
            int h = gi >> 5, d4 = (gi & 31) * 4;
            float4 v = *(const float4*)&fcw[((size_t)e * HDIM + hc * 128 + h) * DE + d4];
            __nv_bfloat16 h0 = __float2bfloat16_rn(v.x), h1 = __float2bfloat16_rn(v.y);
            __nv_bfloat16 h2 = __float2bfloat16_rn(v.z), h3 = __float2bfloat16_rn(v.w);
            uint32_t o = (uint32_t)(h * ROWB + d4 * 2);
            *(unsigned long long*)(sm + OFF_BH + o) =
                pack4bf(__bfloat162float(h0), __bfloat162float(h1),
                        __bfloat162float(h2), __bfloat162float(h3));
            *(unsigned long long*)(sm + OFF_BL + o) =
                pack4bf(v.x - __bfloat162float(h0), v.y - __bfloat162float(h1),
                        v.z - __bfloat162float(h2), v.w - __bfloat162float(h3));
        }
        __syncthreads();

        // ---- GEMM1: D1 = A1 * W1^T  (3 split passes)
        float d1[16][4];
#pragma unroll
        for (int i = 0; i < 16; i++)
#pragma unroll
            for (int q = 0; q < 4; q++) d1[i][q] = 0.0f;

        mma_pass(sm + OFF_A1H, sm + OFF_BH, d1, row0, col0, g, c);
        mma_pass(sm + OFF_A1H, sm + OFF_BL, d1, row0, col0, g, c);
        mma_pass(sm + OFF_A1L, sm + OFF_BH, d1, row0, col0, g, c);
        __syncthreads();   // done reading B (and A2 from prev chunk)

        // ---- epilogue: bias + exact gelu -> A2 hi/lo [tok][h_local]
#pragma unroll
        for (int mt = 0; mt < 2; mt++)
#pragma unroll
            for (int nt = 0; nt < 8; nt++) {
                float* dv = d1[mt * 8 + nt];
                int col = col0 + nt * 8 + 2 * c;
                float b0 = fcb[e * HDIM + hc * 128 + col];
                float b1 = fcb[e * HDIM + hc * 128 + col + 1];
#pragma unroll
                for (int hrow = 0; hrow < 2; hrow++) {
                    int r = row0 + 16 * mt + g + 8 * hrow;
                    float v0 = dv[2 * hrow] + b0;
                    float v1 = dv[2 * hrow + 1] + b1;
                    v0 = 0.5f * v0 * (1.0f + erff(v0 * 0.70710678118654752440f));
                    v1 = 0.5f * v1 * (1.0f + erff(v1 * 0.70710678118654752440f));
                    __nv_bfloat16 h0 = __float2bfloat16_rn(v0);
                    __nv_bfloat16 h1 = __float2bfloat16_rn(v1);
                    uint32_t o = (uint32_t)(r * ROWB + col * 2);
                    *(uint32_t*)(sm + OFF_A2H + o) =
                        pack2bf(__bfloat162float(h0), __bfloat162float(h1));
                    *(uint32_t*)(sm + OFF_A2L + o) =
                        pack2bf(v0 - __bfloat162float(h0),
                                v1 - __bfloat162float(h1));
                }
            }

        // ---- B := proj_w chunk [dd 128][h 128], hi/lo split
        for (int gi = tid; gi < 128 * 32; gi += 256) {
            int dd = gi >> 5, h4 = (gi & 31) * 4;
            float4 v = *(const float4*)&pjw[((size_t)e * DE + dd) * HDIM + hc * 128 + h4];
            __nv_bfloat16 h0 = __float2bfloat16_rn(v.x), h1 = __float2bfloat16_rn(v.y);
            __nv_bfloat16 h2 = __float2bfloat16_rn(v.z), h3 = __float2bfloat16_rn(v.w);
            uint32_t o = (uint32_t)(dd * ROWB + h4 * 2);
            *(unsigned long long*)(sm + OFF_BH + o) =
                pack4bf(__bfloat162float(h0), __bfloat162float(h1),
                        __bfloat162float(h2), __bfloat162float(h3));
            *(unsigned long long*)(sm + OFF_BL + o) =
                pack4bf(v.x - __bfloat162float(h0), v.y - __bfloat162float(h1),
                        v.z - __bfloat162float(h2), v.w - __bfloat162float(h3));
        }
        __syncthreads();   // A2 writes + new B visible to all warps

        // ---- GEMM2: D2 += A2 * W2^T  (persistent accum across chunks)
        mma_pass(sm + OFF_A2H, sm + OFF_BH, d2, row0, col0, g, c);
        mma_pass(sm + OFF_A2H, sm + OFF_BL, d2, row0, col0, g, c);
        mma_pass(sm + OFF_A2L, sm + OFF_BH, d2, row0, col0, g, c);
        __syncthreads();   // B/A2 safe to overwrite next chunk
    }

    // ---- final: D2 + proj_b -> out (active tokens: gate weight exactly 1)
#pragma unroll
    for (int mt = 0; mt < 2; mt++)
#pragma unroll
        for (int nt = 0; nt < 8; nt++) {
            float* dv = d2[mt * 8 + nt];
            int col = col0 + nt * 8 + 2 * c;
            float b0 = pjb[e * DE + col];
            float b1 = pjb[e * DE + col + 1];
#pragma unroll
            for (int hrow = 0; hrow < 2; hrow++) {
                int r = row0 + 16 * mt + g + 8 * hrow;
                int t = toks[r];
                if (t < 0) continue;
                float2 o;
                o.x = dv[2 * hrow] + b0;
                o.y = dv[2 * hrow + 1] + b1;
                *(float2*)&out[(size_t)t * CDIM + e * DE + col] = o;
            }
        }
}

// ---------------- launch ----------------------------------------------------
extern "C" void kernel_launch(void* const* d_in, const int* in_sizes, int n_in,
                              void* d_out, int out_size)
{
    const float* x   = (const float*)d_in[0];
    const float* gw  = (const float*)d_in[1];
    const float* gb  = (const float*)d_in[2];
    const float* fcw = (const float*)d_in[3];
    const float* fcb = (const float*)d_in[4];
    const float* pjw = (const float*)d_in[5];
    const float* pjb = (const float*)d_in[6];
    float* out = (float*)d_out;

    init_kernel<<<1, 32>>>();
    gate_kernel<<<NTOK / GT, 128>>>(x, gw, gb, out);

    cudaFuncSetAttribute(expert_kernel,
                         cudaFuncAttributeMaxDynamicSharedMemorySize,
                         SMEM_TOTAL);
    dim3 grid(NTOK / MT, NE);
    expert_kernel<<<grid, 256, SMEM_TOTAL>>>(x, fcw, fcb, pjw, pjb, out);
}

// round 13
// speedup vs baseline: 1.4082x; 1.0928x over previous
#include <cuda_runtime.h>
#include <cuda_bf16.h>
#include <math.h>
#include <stdint.h>

#define NTOK 16384
#define CDIM 2048
#define NE   16
#define DE   128
#define HDIM 512

// ---------------- device scratch (statics: no allocs allowed) ---------------
__device__ int g_count[NE];
__device__ int g_list[NE][NTOK];
// pre-converted bf16 hi/lo weights (8 MB total)
__device__ __nv_bfloat16 g_fch[NE * HDIM * DE];
__device__ __nv_bfloat16 g_fcl[NE * HDIM * DE];
__device__ __nv_bfloat16 g_pjh[NE * 4 * DE * 128];  // [e][hc][dd][h_local]
__device__ __nv_bfloat16 g_pjl[NE * 4 * DE * 128];

__global__ void cleanup_kernel() {
    if (threadIdx.x < NE) g_count[threadIdx.x] = 0;
}

// ---------------- weight pre-conversion ------------------------------------
__device__ __forceinline__ unsigned long long split4(float4 v,
                                                     unsigned long long& lo64) {
    __nv_bfloat16 h0 = __float2bfloat16_rn(v.x), h1 = __float2bfloat16_rn(v.y);
    __nv_bfloat16 h2 = __float2bfloat16_rn(v.z), h3 = __float2bfloat16_rn(v.w);
    __nv_bfloat162 lA = __floats2bfloat162_rn(v.x - __bfloat162float(h0),
                                              v.y - __bfloat162float(h1));
    __nv_bfloat162 lB = __floats2bfloat162_rn(v.z - __bfloat162float(h2),
                                              v.w - __bfloat162float(h3));
    __nv_bfloat162 hA; hA.x = h0; hA.y = h1;
    __nv_bfloat162 hB; hB.x = h2; hB.y = h3;
    lo64 = (unsigned long long)(*(unsigned int*)&lA)
         | ((unsigned long long)(*(unsigned int*)&lB) << 32);
    return (unsigned long long)(*(unsigned int*)&hA)
         | ((unsigned long long)(*(unsigned int*)&hB) << 32);
}

__global__ __launch_bounds__(256) void wconv_kernel(
    const float* __restrict__ fcw, const float* __restrict__ pjw)
{
    int i = blockIdx.x * 256 + threadIdx.x;   // float4 index, 0..262143
    // fc: natural layout [e][h][d] is already tile-contiguous
    {
        float4 v = ((const float4*)fcw)[i];
        unsigned long long lo, hi = split4(v, lo);
        ((unsigned long long*)g_fch)[i] = hi;
        ((unsigned long long*)g_fcl)[i] = lo;
    }
    // pj: [e][dd][h] -> [e][hc][dd][h_local] tile-contiguous
    {
        float4 v = ((const float4*)pjw)[i];
        int h0 = (i & 127) * 4;
        int dd = (i >> 7) & 127;
        int e  = i >> 14;
        size_t dst = ((((size_t)(e * 4 + (h0 >> 7)) * 128 + dd) * 128
                       + (h0 & 127)) >> 2);
        unsigned long long lo, hi = split4(v, lo);
        ((unsigned long long*)g_pjh)[dst] = hi;
        ((unsigned long long*)g_pjl)[dst] = lo;
    }
}

// ======================= gate (exact path) ==================================
#define GT  128
#define GKC 64
__device__ __forceinline__ unsigned long long pk2(float a, float b) {
    unsigned long long r;
    asm("mov.b64 %0, {%1, %2};" : "=l"(r) : "f"(a), "f"(b));
    return r;
}
__device__ __forceinline__ void upk2(unsigned long long v, float& a, float& b) {
    asm("mov.b64 {%0, %1}, %2;" : "=f"(a), "=f"(b) : "l"(v));
}
#define FMA2(acc, a, b) \
    asm("fma.rn.f32x2 %0, %1, %2, %0;" : "+l"(acc) : "l"(a), "l"(b))

__global__ __launch_bounds__(128) void gate_kernel(
    const float* __restrict__ x, const float* __restrict__ gw,
    const float* __restrict__ gb, float* __restrict__ out)
{
    __shared__ float xs[GKC][GT + 4];
    __shared__ float ws[GKC][NE];
    __shared__ unsigned char act[GT][NE];

    const int tid  = threadIdx.x;
    const int t0   = blockIdx.x * GT;
    const int tok4 = (tid & 31) * 4;
    const int e4   = (tid >> 5) * 4;

    double acc[4][4];
#pragma unroll
    for (int i = 0; i < 4; i++)
#pragma unroll
        for (int j = 0; j < 4; j++) acc[i][j] = 0.0;

    for (int c0 = 0; c0 < CDIM; c0 += GKC) {
        for (int i = tid; i < GT * GKC; i += 128) {
            int t = i >> 6, c = i & 63;
            xs[c][t] = x[(size_t)(t0 + t) * CDIM + c0 + c];
        }
        for (int i = tid; i < NE * GKC; i += 128) {
            int e = i >> 6, c = i & 63;
            ws[c][e] = gw[e * CDIM + c0 + c];
        }
        __syncthreads();

        unsigned long long f2[4][2];
#pragma unroll
        for (int i = 0; i < 4; i++) { f2[i][0] = 0ull; f2[i][1] = 0ull; }

#pragma unroll 8
        for (int c = 0; c < GKC; c++) {
            float4 xv = *(const float4*)&xs[c][tok4];
            ulonglong2 wv = *(const ulonglong2*)&ws[c][e4];
            unsigned long long b0 = pk2(xv.x, xv.x);
            unsigned long long b1 = pk2(xv.y, xv.y);
            unsigned long long b2 = pk2(xv.z, xv.z);
            unsigned long long b3 = pk2(xv.w, xv.w);
            FMA2(f2[0][0], b0, wv.x); FMA2(f2[0][1], b0, wv.y);
            FMA2(f2[1][0], b1, wv.x); FMA2(f2[1][1], b1, wv.y);
            FMA2(f2[2][0], b2, wv.x); FMA2(f2[2][1], b2, wv.y);
            FMA2(f2[3][0], b3, wv.x); FMA2(f2[3][1], b3, wv.y);
        }
#pragma unroll
        for (int i = 0; i < 4; i++)
#pragma unroll
            for (int jp = 0; jp < 2; jp++) {
                float lo, hi; upk2(f2[i][jp], lo, hi);
                acc[i][2 * jp]     += (double)lo;
                acc[i][2 * jp + 1] += (double)hi;
            }
        __syncthreads();
    }

#pragma unroll
    for (int i = 0; i < 4; i++)
#pragma unroll
        for (int j = 0; j < 4; j++) {
            float l = (float)acc[i][j] + gb[e4 + j];
            act[tok4 + i][e4 + j] = (l > 0.0f) ? 1 : 0;
        }
    __syncthreads();

    for (int i = tid; i < GT * NE * (DE / 4); i += 128) {
        int pair = i >> 5, q = i & 31;
        int t = pair >> 4, e = pair & 15;
        if (!act[t][e]) {
            float4 z = make_float4(0.f, 0.f, 0.f, 0.f);
            *(float4*)&out[(size_t)(t0 + t) * CDIM + e * DE + q * 4] = z;
        }
    }
    if (tid < NE) {
        int e = tid, cnt = 0;
        for (int t = 0; t < GT; t++) cnt += act[t][e];
        int base = atomicAdd(&g_count[e], cnt);
        for (int t = 0; t < GT; t++)
            if (act[t][e]) g_list[e][base++] = t0 + t;
    }
}

// ======================= expert MLP: mma.sync + cp.async pipeline ===========
// Block = (expert, 64-token tile), 256 thr / 8 warps.
// Warp tile = 32 tok x 32 cols. Weights pre-converted; fc/pj chunks prefetched
// via cp.async one phase ahead. 3-way bf16 split per GEMM.
#define MT 64
#define ROWB 272                   // row stride bytes (bank-shift 4)
#define A_TILE (64 * ROWB)         // 17408
#define B_TILE (128 * ROWB)        // 34816

#define OFF_A1H 0
#define OFF_A1L (OFF_A1H + A_TILE)
#define OFF_A2H (OFF_A1L + A_TILE)
#define OFF_A2L (OFF_A2H + A_TILE)
#define OFF_FCH (OFF_A2L + A_TILE)
#define OFF_FCL (OFF_FCH + B_TILE)
#define OFF_PJH (OFF_FCL + B_TILE)
#define OFF_PJL (OFF_PJH + B_TILE)
#define OFF_TOK (OFF_PJL + B_TILE)
#define SMEM_TOTAL (OFF_TOK + 256 + 128)

#define CP16(dst, src) \
    asm volatile("cp.async.cg.shared.global [%0], [%1], 16;" \
                 :: "r"(dst), "l"(src))
#define CP_COMMIT() asm volatile("cp.async.commit_group;" ::: "memory")
#define CP_WAIT1()  asm volatile("cp.async.wait_group 1;" ::: "memory")
#define CP_WAIT0()  asm volatile("cp.async.wait_group 0;" ::: "memory")

__device__ __forceinline__ uint32_t smem_u32(const void* p) {
    uint32_t a;
    asm("{ .reg .u64 t; cvta.to.shared.u64 t, %1; cvt.u32.u64 %0, t; }"
        : "=r"(a) : "l"(p));
    return a;
}

__device__ __forceinline__ void mma16816(float* d, const uint32_t* a,
                                         const uint32_t* b) {
    asm volatile(
        "mma.sync.aligned.m16n8k16.row.col.f32.bf16.bf16.f32 "
        "{%0,%1,%2,%3}, {%4,%5,%6,%7}, {%8,%9}, {%0,%1,%2,%3};"
        : "+f"(d[0]), "+f"(d[1]), "+f"(d[2]), "+f"(d[3])
        : "r"(a[0]), "r"(a[1]), "r"(a[2]), "r"(a[3]), "r"(b[0]), "r"(b[1]));
}
__device__ __forceinline__ uint32_t pack2bf(float a, float b) {
    __nv_bfloat162 p = __floats2bfloat162_rn(a, b);
    return *(uint32_t*)&p;
}

// copy one 128x128 bf16 tile (32 KB contiguous global) to padded smem
__device__ __forceinline__ void tile_cp(uint32_t sdst,
                                        const __nv_bfloat16* gsrc, int tid) {
#pragma unroll
    for (int k = 0; k < 8; k++) {
        int i = tid + k * 256;           // 16B unit: row = i>>4, col16 = i&15
        uint32_t d = sdst + (uint32_t)((i >> 4) * ROWB + (i & 15) * 16);
        CP16(d, (const char*)gsrc + (size_t)i * 16);
    }
}

// one (A,B) MMA pass over a 128-K chunk: warp tile 32 tok x 32 cols
__device__ __forceinline__ void mma_pass(const char* __restrict__ A,
                                         const char* __restrict__ B,
                                         float (*d)[4], int row0, int ncol0,
                                         int g, int c) {
#pragma unroll
    for (int kt = 0; kt < 8; kt++) {
        uint32_t a[2][4];
        const char* ar = A + (row0 + g) * ROWB + kt * 32 + c * 4;
#pragma unroll
        for (int mt = 0; mt < 2; mt++) {
            const char* am = ar + mt * (16 * ROWB);
            a[mt][0] = *(const uint32_t*)(am);
            a[mt][1] = *(const uint32_t*)(am + 8 * ROWB);
            a[mt][2] = *(const uint32_t*)(am + 16);
            a[mt][3] = *(const uint32_t*)(am + 8 * ROWB + 16);
        }
#pragma unroll
        for (int nt = 0; nt < 4; nt++) {
            const char* br = B + (ncol0 + nt * 8 + g) * ROWB + kt * 32 + c * 4;
            uint32_t b[2];
            b[0] = *(const uint32_t*)(br);
            b[1] = *(const uint32_t*)(br + 16);
            mma16816(d[nt], a[0], b);
            mma16816(d[4 + nt], a[1], b);
        }
    }
}

__global__ __launch_bounds__(256) void expert_kernel(
    const float* __restrict__ x,
    const float* __restrict__ fcb, const float* __restrict__ pjb,
    float* __restrict__ out)
{
    const int e   = blockIdx.y;
    const int cnt = g_count[e];
    const int i0  = blockIdx.x * MT;
    if (i0 >= cnt) return;

    extern __shared__ char sm[];
    const uint32_t smb = smem_u32(sm);
    int* toks = (int*)(sm + OFF_TOK);

    const int tid  = threadIdx.x;
    const int wid  = tid >> 5;
    const int lane = tid & 31;
    const int g    = lane >> 2;
    const int c    = lane & 3;
    const int row0 = 32 * (wid & 1);
    const int col0 = 32 * (wid >> 1);

    // prologue: prefetch fc[0] (group 0) and pj[0] (group 1)
    tile_cp(smb + OFF_FCH, g_fch + ((size_t)e * HDIM) * DE, tid);
    tile_cp(smb + OFF_FCL, g_fcl + ((size_t)e * HDIM) * DE, tid);
    CP_COMMIT();
    tile_cp(smb + OFF_PJH, g_pjh + (size_t)(e * 4) * DE * 128, tid);
    tile_cp(smb + OFF_PJL, g_pjl + (size_t)(e * 4) * DE * 128, tid);
    CP_COMMIT();

    if (tid < MT) {
        int idx = i0 + tid;
        toks[tid] = (idx < cnt) ? g_list[e][idx] : -1;
    }
    __syncthreads();   // toks visible

    // A1: gather x strided channels, hi/lo split
    for (int i = tid; i < MT * DE; i += 256) {
        int j = i & 63, d = i >> 6;
        int t = toks[j];
        float f = (t >= 0) ? x[(size_t)t * CDIM + d * NE + e] : 0.0f;
        __nv_bfloat16 hb = __float2bfloat16_rn(f);
        uint32_t o = (uint32_t)(j * ROWB + d * 2);
        *(__nv_bfloat16*)(sm + OFF_A1H + o) = hb;
        *(__nv_bfloat16*)(sm + OFF_A1L + o) =
            __float2bfloat16_rn(f - __bfloat162float(hb));
    }

    float d2[8][4];
#pragma unroll
    for (int i = 0; i < 8; i++)
#pragma unroll
        for (int q = 0; q < 4; q++) d2[i][q] = 0.0f;

    for (int hc = 0; hc < 4; hc++) {
        CP_WAIT1();          // fc[hc] resident (pj[hc] may still fly)
        __syncthreads();

        float d1[8][4];
#pragma unroll
        for (int i = 0; i < 8; i++)
#pragma unroll
            for (int q = 0; q < 4; q++) d1[i][q] = 0.0f;
        mma_pass(sm + OFF_A1H, sm + OFF_FCH, d1, row0, col0, g, c);
        mma_pass(sm + OFF_A1H, sm + OFF_FCL, d1, row0, col0, g, c);
        mma_pass(sm + OFF_A1L, sm + OFF_FCH, d1, row0, col0, g, c);
        __syncthreads();     // done reading FC + prev A2

        if (hc < 3) {        // prefetch fc[hc+1] into freed FC buffers
            size_t b = ((size_t)e * HDIM + (hc + 1) * 128) * DE;
            tile_cp(smb + OFF_FCH, g_fch + b, tid);
            tile_cp(smb + OFF_FCL, g_fcl + b, tid);
            CP_COMMIT();
        }

        // epilogue: bias + exact gelu -> A2 hi/lo
#pragma unroll
        for (int mt = 0; mt < 2; mt++)
#pragma unroll
            for (int nt = 0; nt < 4; nt++) {
                float* dv = d1[mt * 4 + nt];
                int col = col0 + nt * 8 + 2 * c;
                float b0 = fcb[e * HDIM + hc * 128 + col];
                float b1 = fcb[e * HDIM + hc * 128 + col + 1];
#pragma unroll
                for (int hrow = 0; hrow < 2; hrow++) {
                    int r = row0 + 16 * mt + g + 8 * hrow;
                    float v0 = dv[2 * hrow] + b0;
                    float v1 = dv[2 * hrow + 1] + b1;
                    v0 = 0.5f * v0 * (1.0f + erff(v0 * 0.70710678118654752440f));
                    v1 = 0.5f * v1 * (1.0f + erff(v1 * 0.70710678118654752440f));
                    __nv_bfloat16 h0 = __float2bfloat16_rn(v0);
                    __nv_bfloat16 h1 = __float2bfloat16_rn(v1);
                    uint32_t o = (uint32_t)(r * ROWB + col * 2);
                    *(uint32_t*)(sm + OFF_A2H + o) =
                        pack2bf(__bfloat162float(h0), __bfloat162float(h1));
                    *(uint32_t*)(sm + OFF_A2L + o) =
                        pack2bf(v0 - __bfloat162float(h0),
                                v1 - __bfloat162float(h1));
                }
            }

        if (hc < 3) { CP_WAIT1(); } else { CP_WAIT0(); }  // pj[hc] resident
        __syncthreads();     // + A2 visible

        mma_pass(sm + OFF_A2H, sm + OFF_PJH, d2, row0, col0, g, c);
        mma_pass(sm + OFF_A2H, sm + OFF_PJL, d2, row0, col0, g, c);
        mma_pass(sm + OFF_A2L, sm + OFF_PJH, d2, row0, col0, g, c);
        __syncthreads();     // done reading PJ

        if (hc < 3) {        // prefetch pj[hc+1]
            size_t b = (size_t)(e * 4 + hc + 1) * DE * 128;
            tile_cp(smb + OFF_PJH, g_pjh + b, tid);
            tile_cp(smb + OFF_PJL, g_pjl + b, tid);
            CP_COMMIT();
        }
    }

    // final: D2 + proj_b -> out (active tokens: gate weight exactly 1)
#pragma unroll
    for (int mt = 0; mt < 2; mt++)
#pragma unroll
        for (int nt = 0; nt < 4; nt++) {
            float* dv = d2[mt * 4 + nt];
            int col = col0 + nt * 8 + 2 * c;
            float b0 = pjb[e * DE + col];
            float b1 = pjb[e * DE + col + 1];
#pragma unroll
            for (int hrow = 0; hrow < 2; hrow++) {
                int r = row0 + 16 * mt + g + 8 * hrow;
                int t = toks[r];
                if (t < 0) continue;
                float2 o;
                o.x = dv[2 * hrow] + b0;
                o.y = dv[2 * hrow + 1] + b1;
                *(float2*)&out[(size_t)t * CDIM + e * DE + col] = o;
            }
        }
}

// ---------------- launch ----------------------------------------------------
extern "C" void kernel_launch(void* const* d_in, const int* in_sizes, int n_in,
                              void* d_out, int out_size)
{
    const float* x   = (const float*)d_in[0];
    const float* gw  = (const float*)d_in[1];
    const float* gb  = (const float*)d_in[2];
    const float* fcw = (const float*)d_in[3];
    const float* fcb = (const float*)d_in[4];
    const float* pjw = (const float*)d_in[5];
    const float* pjb = (const float*)d_in[6];
    float* out = (float*)d_out;

    // g_count starts zeroed (module init); cleanup re-zeroes for next replay.
    gate_kernel<<<NTOK / GT, 128>>>(x, gw, gb, out);
    wconv_kernel<<<1024, 256>>>(fcw, pjw);

    cudaFuncSetAttribute(expert_kernel,
                         cudaFuncAttributeMaxDynamicSharedMemorySize,
                         SMEM_TOTAL);
    dim3 grid(NTOK / MT, NE);
    expert_kernel<<<grid, 256, SMEM_TOTAL>>>(x, fcb, pjb, out);

    cleanup_kernel<<<1, 32>>>();
}